// round 4
// baseline (speedup 1.0000x reference)
#include <cuda_runtime.h>
#include <cstdint>

#define N_NODES 500000

// Static device scratch (allocation-free rule):
// g_cs[i]  = (cos theta_i, sin theta_i)   -- 4 MB gather table
// g_acc[i] = sum over incoming edges of e^{i theta_src}  -- 4 MB accumulator
__device__ float2 g_cs[N_NODES];
__device__ float2 g_acc[N_NODES];

// ---------------------------------------------------------------------------
// Kernel 1: build (cos,sin) table + zero the accumulator (4 nodes/thread)
// ---------------------------------------------------------------------------
__global__ void init_kernel(const float* __restrict__ theta, int n) {
    int i4 = blockIdx.x * blockDim.x + threadIdx.x;   // group of 4 nodes
    int base = i4 * 4;
    if (base + 3 < n) {
        float4 t = __ldg((const float4*)(theta + base));
        float s0, c0, s1, c1, s2, c2, s3, c3;
        __sincosf(t.x, &s0, &c0);
        __sincosf(t.y, &s1, &c1);
        __sincosf(t.z, &s2, &c2);
        __sincosf(t.w, &s3, &c3);
        float4* cs4 = (float4*)(g_cs + base);
        cs4[0] = make_float4(c0, s0, c1, s1);
        cs4[1] = make_float4(c2, s2, c3, s3);
        float4* ac4 = (float4*)(g_acc + base);
        ac4[0] = make_float4(0.f, 0.f, 0.f, 0.f);
        ac4[1] = make_float4(0.f, 0.f, 0.f, 0.f);
    } else {
        for (int i = base; i < n; i++) {
            float sn, cs;
            __sincosf(theta[i], &sn, &cs);
            g_cs[i]  = make_float2(cs, sn);
            g_acc[i] = make_float2(0.f, 0.f);
        }
    }
}

// ---------------------------------------------------------------------------
// Kernel 2: edge kernel.
// sum_{e->d} e^{i(ts-td)} = e^{-i td} * sum_{e->d} e^{i ts}  -- so each edge
// gathers only e^{i theta[src]} (8B) and REDs it into acc[dst]. Deep 3-phase
// batching: 16 coalesced index-int4 loads, then 16 random gathers in flight,
// then 16 REDs.
// ---------------------------------------------------------------------------
__global__ void __launch_bounds__(256) edge_kernel(
        const int4* __restrict__ src4,
        const int4* __restrict__ dst4,
        int n4,
        const int* __restrict__ src_tail,
        const int* __restrict__ dst_tail,
        int n_tail) {
    const int U = 4;  // int4 groups per thread => 16 edges
    long long base = (long long)blockIdx.x * blockDim.x * U + threadIdx.x;

    int4   s[U], d[U];
    bool   ok[U];
    float2 m[U][4];

    // Phase 1: coalesced 16B index loads
    #pragma unroll
    for (int u = 0; u < U; u++) {
        long long g = base + (long long)u * blockDim.x;
        ok[u] = (g < n4);
        if (ok[u]) {
            s[u] = __ldg(&src4[g]);
            d[u] = __ldg(&dst4[g]);
        }
    }

    // Phase 2: 16 independent random gathers (maximize MLP)
    #pragma unroll
    for (int u = 0; u < U; u++) {
        if (ok[u]) {
            m[u][0] = __ldg(&g_cs[s[u].x]);
            m[u][1] = __ldg(&g_cs[s[u].y]);
            m[u][2] = __ldg(&g_cs[s[u].z]);
            m[u][3] = __ldg(&g_cs[s[u].w]);
        }
    }

    // Phase 3: vector reductions (float2 atomicAdd -> RED .64)
    #pragma unroll
    for (int u = 0; u < U; u++) {
        if (ok[u]) {
            atomicAdd(&g_acc[d[u].x], m[u][0]);
            atomicAdd(&g_acc[d[u].y], m[u][1]);
            atomicAdd(&g_acc[d[u].z], m[u][2]);
            atomicAdd(&g_acc[d[u].w], m[u][3]);
        }
    }

    // Tail edges (n_edges % 4)
    if (blockIdx.x == 0 && threadIdx.x < n_tail) {
        int sidx = __ldg(&src_tail[threadIdx.x]);
        int didx = __ldg(&dst_tail[threadIdx.x]);
        atomicAdd(&g_acc[didx], __ldg(&g_cs[sidx]));
    }
}

// ---------------------------------------------------------------------------
// Kernel 3: node epilogue, 2 nodes/thread (float4-vectorized).
//   v[i]      = v0 * (cos t, sin t)
//   torque[i] = w0 * (c*S.y - s*S.x) / max(|S|, eps)
// (rotation by e^{-i t} preserves the norm; mean==sum under normalize)
// ---------------------------------------------------------------------------
__global__ void node_kernel(const float* __restrict__ v0p,
                            const float* __restrict__ w0p,
                            float* __restrict__ out,
                            int n) {
    int i2 = blockIdx.x * blockDim.x + threadIdx.x;  // pair of nodes
    int i = i2 * 2;
    if (i >= n) return;

    float v0 = __ldg(v0p);
    float w0 = __ldg(w0p);

    if (i + 1 < n) {
        float4 cs = __ldg((const float4*)(g_cs + i));   // (c0,s0,c1,s1)
        float4 S  = *((const float4*)(g_acc + i));      // (x0,y0,x1,y1)

        *((float4*)(out + 2 * i)) =
            make_float4(v0 * cs.x, v0 * cs.y, v0 * cs.z, v0 * cs.w);

        float y0 = cs.x * S.y - cs.y * S.x;
        float n0 = sqrtf(S.x * S.x + S.y * S.y);
        float y1 = cs.z * S.w - cs.w * S.z;
        float n1 = sqrtf(S.z * S.z + S.w * S.w);
        *((float2*)(out + 2 * n + i)) =
            make_float2(w0 * (y0 / fmaxf(n0, 1e-12f)),
                        w0 * (y1 / fmaxf(n1, 1e-12f)));
    } else {
        float2 cs = g_cs[i];
        float2 S  = g_acc[i];
        out[2 * i + 0] = v0 * cs.x;
        out[2 * i + 1] = v0 * cs.y;
        float y   = cs.x * S.y - cs.y * S.x;
        float nrm = sqrtf(S.x * S.x + S.y * S.y);
        out[2 * n + i] = w0 * (y / fmaxf(nrm, 1e-12f));
    }
}

// ---------------------------------------------------------------------------
extern "C" void kernel_launch(void* const* d_in, const int* in_sizes, int n_in,
                              void* d_out, int out_size) {
    const float* theta = (const float*)d_in[0];
    const int*   src   = (const int*)d_in[1];
    const int*   dst   = (const int*)d_in[2];
    const float* v0p   = (const float*)d_in[3];
    const float* w0p   = (const float*)d_in[4];
    float*       out   = (float*)d_out;

    int n_nodes = in_sizes[0];
    int n_edges = in_sizes[1];
    int n4      = n_edges / 4;
    int n_tail  = n_edges - n4 * 4;

    {
        int threads = 256;
        int groups = (n_nodes + 3) / 4;
        int blocks = (groups + threads - 1) / threads;
        init_kernel<<<blocks, threads>>>(theta, n_nodes);
    }
    {
        const int U = 4;
        int threads = 256;
        long long per_block = (long long)threads * U;
        int blocks = (int)(((long long)n4 + per_block - 1) / per_block);
        if (blocks < 1) blocks = 1;
        edge_kernel<<<blocks, threads>>>((const int4*)src, (const int4*)dst, n4,
                                         src + n4 * 4, dst + n4 * 4, n_tail);
    }
    {
        int threads = 256;
        int pairs = (n_nodes + 1) / 2;
        int blocks = (pairs + threads - 1) / threads;
        node_kernel<<<blocks, threads>>>(v0p, w0p, out, n_nodes);
    }
}

// round 5
// speedup vs baseline: 1.7099x; 1.7099x over previous
#include <cuda_runtime.h>
#include <cstdint>

#define N_NODES 500000

// Static device scratch (allocation-free rule):
// g_cs[i]  = (cos theta_i, sin theta_i)   -- 4 MB gather table
// g_acc[i] = sum over incoming edges of e^{i theta_src}  -- 4 MB accumulator
__device__ float2 g_cs[N_NODES];
__device__ float2 g_acc[N_NODES];

// ---------------------------------------------------------------------------
// Kernel 1: build (cos,sin) table + zero the accumulator (R3-proven scalar)
// ---------------------------------------------------------------------------
__global__ void init_kernel(const float* __restrict__ theta, int n) {
    int i = blockIdx.x * blockDim.x + threadIdx.x;
    if (i < n) {
        float sn, cs;
        __sincosf(theta[i], &sn, &cs);
        g_cs[i]  = make_float2(cs, sn);
        g_acc[i] = make_float2(0.f, 0.f);
    }
}

// ---------------------------------------------------------------------------
// Kernel 2: edge kernel (R3-proven U=2 shape).
// sum_{e->d} e^{i(ts-td)} = e^{-i td} * sum_{e->d} e^{i ts}: per edge, gather
// only e^{i theta[src]} (8B) and RED it into acc[dst]. Index loads use
// streaming hint (__ldcs) so the 128MB index stream doesn't evict the 4MB
// gather table from L1.
// ---------------------------------------------------------------------------
__global__ void __launch_bounds__(256) edge_kernel(
        const int4* __restrict__ src4,
        const int4* __restrict__ dst4,
        int n4,
        const int* __restrict__ src_tail,
        const int* __restrict__ dst_tail,
        int n_tail) {
    const int U = 2;  // int4 groups per thread => 8 edges
    long long base = (long long)blockIdx.x * blockDim.x * U + threadIdx.x;

    int4   s[U], d[U];
    bool   ok[U];
    float2 m[U][4];

    // Phase 1: coalesced 16B index loads (streaming — single-use data)
    #pragma unroll
    for (int u = 0; u < U; u++) {
        long long g = base + (long long)u * blockDim.x;
        ok[u] = (g < n4);
        if (ok[u]) {
            s[u] = __ldcs(&src4[g]);
            d[u] = __ldcs(&dst4[g]);
        }
    }

    // Phase 2: 8 independent random gathers (MLP without queue-thrash)
    #pragma unroll
    for (int u = 0; u < U; u++) {
        if (ok[u]) {
            m[u][0] = __ldg(&g_cs[s[u].x]);
            m[u][1] = __ldg(&g_cs[s[u].y]);
            m[u][2] = __ldg(&g_cs[s[u].z]);
            m[u][3] = __ldg(&g_cs[s[u].w]);
        }
    }

    // Phase 3: vector reductions (float2 atomicAdd -> RED .64)
    #pragma unroll
    for (int u = 0; u < U; u++) {
        if (ok[u]) {
            atomicAdd(&g_acc[d[u].x], m[u][0]);
            atomicAdd(&g_acc[d[u].y], m[u][1]);
            atomicAdd(&g_acc[d[u].z], m[u][2]);
            atomicAdd(&g_acc[d[u].w], m[u][3]);
        }
    }

    // Tail edges (n_edges % 4): spread across the grid, one per thread-slot
    long long tslot = (long long)blockIdx.x * blockDim.x + threadIdx.x;
    if (tslot < n_tail) {
        int sidx = __ldg(&src_tail[tslot]);
        int didx = __ldg(&dst_tail[tslot]);
        atomicAdd(&g_acc[didx], __ldg(&g_cs[sidx]));
    }
}

// ---------------------------------------------------------------------------
// Kernel 3: node epilogue (R3-proven scalar, float2 store for v).
//   v[i]      = v0 * (cos t, sin t)
//   torque[i] = w0 * (c*S.y - s*S.x) / max(|S|, eps)
// (rotation by e^{-i t} preserves the norm; mean==sum under normalize)
// ---------------------------------------------------------------------------
__global__ void node_kernel(const float* __restrict__ v0p,
                            const float* __restrict__ w0p,
                            float* __restrict__ out,
                            int n) {
    int i = blockIdx.x * blockDim.x + threadIdx.x;
    if (i >= n) return;

    float v0 = __ldg(v0p);
    float w0 = __ldg(w0p);

    float2 cs = g_cs[i];
    *((float2*)(out + 2 * i)) = make_float2(v0 * cs.x, v0 * cs.y);

    float2 S = g_acc[i];
    float y   = cs.x * S.y - cs.y * S.x;
    float nrm = sqrtf(S.x * S.x + S.y * S.y);
    out[2 * n + i] = w0 * (y / fmaxf(nrm, 1e-12f));
}

// ---------------------------------------------------------------------------
extern "C" void kernel_launch(void* const* d_in, const int* in_sizes, int n_in,
                              void* d_out, int out_size) {
    const float* theta = (const float*)d_in[0];
    const int*   src   = (const int*)d_in[1];
    const int*   dst   = (const int*)d_in[2];
    const float* v0p   = (const float*)d_in[3];
    const float* w0p   = (const float*)d_in[4];
    float*       out   = (float*)d_out;

    int n_nodes = in_sizes[0];
    int n_edges = in_sizes[1];
    int n4      = n_edges / 4;
    int n_tail  = n_edges - n4 * 4;

    {
        int threads = 256;
        int blocks = (n_nodes + threads - 1) / threads;
        init_kernel<<<blocks, threads>>>(theta, n_nodes);
    }
    {
        const int U = 2;
        int threads = 256;
        long long per_block = (long long)threads * U;
        int blocks = (int)(((long long)n4 + per_block - 1) / per_block);
        if (blocks < 1) blocks = 1;
        edge_kernel<<<blocks, threads>>>((const int4*)src, (const int4*)dst, n4,
                                         src + n4 * 4, dst + n4 * 4, n_tail);
    }
    {
        int threads = 256;
        int blocks = (n_nodes + threads - 1) / threads;
        node_kernel<<<blocks, threads>>>(v0p, w0p, out, n_nodes);
    }
}